// round 13
// baseline (speedup 1.0000x reference)
#include <cuda_runtime.h>
#include <cuda_fp16.h>
#include <cstdint>

#define NB 512
#define NR 196
#define DV 1024
#define DH 512
#define DA 256
#define KC 64                   // K elements per chunk
#define TPB 256
#define AP 68                   // A smem pitch (fp32 floats)
#define MT 64                   // M tile rows per chunk
#define A_STAGE (MT * AP)       // 4352 floats = 17.4KB; stage = A only (B read direct from L2)
#define NCH 64                  // 4 M-chunks x 16 K-chunks
#define SMEM_FLOATS (2 * A_STAGE + DA + DA + DA + 64 + 8)
#define SMEM_BYTES (SMEM_FLOATS * 4)

__device__ uint32_t g_Wvh[DV * DA / 2];   // fp16 Wv, lane-contiguous frag-major
                                          // [kc32][ks2][wn][lane][nf][b0,b1]
__device__ float g_hproj[NB * DA];

// ---------------- helpers ----------------
static __device__ __forceinline__ uint32_t smem_u32(const void* p) {
    uint32_t a;
    asm("{ .reg .u64 t; cvta.to.shared.u64 t, %1; cvt.u32.u64 %0, t; }" : "=r"(a) : "l"(p));
    return a;
}
static __device__ __forceinline__ void cpa16(uint32_t dst, const void* src) {
    asm volatile("cp.async.cg.shared.global [%0], [%1], 16;" :: "r"(dst), "l"(src));
}
static __device__ __forceinline__ void cpa_commit() {
    asm volatile("cp.async.commit_group;" ::: "memory");
}
template <int N> static __device__ __forceinline__ void cpa_wait() {
    asm volatile("cp.async.wait_group %0;" :: "n"(N) : "memory");
}
static __device__ __forceinline__ void sts_zero16(uint32_t dst) {
    asm volatile("st.shared.v4.b32 [%0], {%1,%1,%1,%1};" :: "r"(dst), "r"(0) : "memory");
}
static __device__ __forceinline__ uint32_t pack_h2(float lo, float hi) {
    __half2 h = __floats2half2_rn(lo, hi);
    return *(uint32_t*)&h;
}
static __device__ __forceinline__ void mma16(float* c, const uint32_t* a, uint32_t b0, uint32_t b1) {
    asm volatile(
        "mma.sync.aligned.m16n8k16.row.col.f32.f16.f16.f32 "
        "{%0,%1,%2,%3}, {%4,%5,%6,%7}, {%8,%9}, {%0,%1,%2,%3};"
        : "+f"(c[0]), "+f"(c[1]), "+f"(c[2]), "+f"(c[3])
        : "r"(a[0]), "r"(a[1]), "r"(a[2]), "r"(a[3]), "r"(b0), "r"(b1));
}

// ---------------- setup: Wv->fp16 lane-contiguous frag-major + hproj ----------------
// u32 entry r = kc32*4096 + ks2*2048 + wn*512 + lane*16 + nf*2 + breg
// col = wn*64+nf*8+(lane>>2);  k0 = kc*32+ks2*16+2*(lane&3)+breg*8
__global__ __launch_bounds__(DA) void setup_kernel(
    const float* __restrict__ Wv,
    const float* __restrict__ hidden, const float* __restrict__ Wh,
    const float* __restrict__ bh)
{
    if (blockIdx.x < 512) {
        const int r = blockIdx.x * DA + threadIdx.x;
        const int breg = r & 1;
        const int nf   = (r >> 1) & 7;
        const int lane = (r >> 4) & 31;
        const int wn   = (r >> 9) & 3;
        const int ks2  = (r >> 11) & 1;
        const int kc   = r >> 12;
        const int col = wn * 64 + nf * 8 + (lane >> 2);
        const int k0  = kc * 32 + ks2 * 16 + 2 * (lane & 3) + breg * 8;
        g_Wvh[r] = pack_h2(Wv[k0 * DA + col], Wv[(k0 + 1) * DA + col]);
    } else {
        const int b = blockIdx.x - 512, a = threadIdx.x;
        const float* h = hidden + b * DH;
        const float* w = Wh + a;
        float acc = bh[a];
#pragma unroll 8
        for (int k = 0; k < DH; k++) acc = fmaf(h[k], w[k * DA], acc);
        g_hproj[b * DA + a] = acc;
    }
}

// ---------------- staging: A only (4 cpa16/thread) ----------------
static __device__ __forceinline__ void stage_chunk(int idx, uint32_t sS,
                                                   const float* __restrict__ vb, int t) {
    const int mc = idx >> 4, kc = idx & 15, buf = idx & 1;
    const int k0 = kc * KC;
    const uint32_t base = sS + (uint32_t)buf * (A_STAGE * 4);
#pragma unroll
    for (int i = 0; i < 4; i++) {                 // A: 64 rows x 16 segs of 16B
        int s = t + i * TPB;
        int row = s >> 4, seg = s & 15;
        int gr = mc * MT + row;
        uint32_t dst = base + row * (AP * 4) + seg * 16;
        if (gr < NR) cpa16(dst, vb + (size_t)gr * DV + k0 + seg * 4);
        else         sts_zero16(dst);
    }
}

// ---------------- fused: 1 CTA/batch, 2 CTAs/SM, B direct L2->reg, online softmax ----------------
__global__ __launch_bounds__(TPB, 2) void fused_kernel(
    const float* __restrict__ visual,
    const float* __restrict__ bv,
    const float* __restrict__ Wa,
    float* __restrict__ out)
{
    extern __shared__ float smem[];
    float* stg  = smem;                          // 2 * A_STAGE
    float* hpS  = smem + 2 * A_STAGE;
    float* waS  = hpS + DA;
    float* scS  = waS + DA;
    float* esS  = scS + DA;                      // 64 exp weights of current chunk
    float* misc = esS + 64;                      // [0]=max,[1]=den,[2]=scale

    const int b = blockIdx.x, t = threadIdx.x;
    const int wid = t >> 5, lane = t & 31, g = lane >> 2, tg = lane & 3;
    const int warp_m = wid >> 2, warp_n = wid & 3;    // 2x4 warps: 64 rows x 256 cols
    const float* vb = visual + (size_t)b * NR * DV;
    const float4* vb4 = (const float4*)vb;

    hpS[t] = g_hproj[b * DA + t] + bv[t];
    waS[t] = Wa[t];
    scS[t] = 0.0f;
    if (t == 0) { misc[0] = -3.0e38f; misc[1] = 0.0f; misc[2] = 0.0f; }

    const uint32_t sS = smem_u32(stg);
    const uint32_t* BgLane = g_Wvh + warp_n * 512 + lane * 16;   // per-lane B base

    stage_chunk(0, sS, vb, t);
    cpa_commit();

    float acc[2][8][4];
#pragma unroll
    for (int mf = 0; mf < 2; mf++)
#pragma unroll
        for (int nf = 0; nf < 8; nf++)
#pragma unroll
            for (int i = 0; i < 4; i++) acc[mf][nf][i] = 0.0f;

    float4 num = make_float4(0.f, 0.f, 0.f, 0.f);

#pragma unroll 1
    for (int mc = 0; mc < 4; mc++) {
        const int nmf = (mc == 3) ? ((warp_m == 0) ? 1 : 0) : 2;

        for (int kc = 0; kc < 16; kc++) {
            const int idx = mc * 16 + kc;
            if (idx) __syncthreads();                  // WAR: restage target buffer drained
            if (idx + 1 < NCH) {
                stage_chunk(idx + 1, sS, vb, t);
                cpa_commit();
                cpa_wait<1>();                         // chunk idx landed (this thread)
            } else {
                cpa_wait<0>();
            }
            __syncthreads();                           // all threads' data landed

            if (nmf > 0) {
                const int buf = idx & 1;
                const float* A = stg + buf * A_STAGE + (warp_m * 32) * AP;
                const uint32_t* Bg = BgLane + (size_t)(2 * (idx & 15)) * 4096;
#pragma unroll
                for (int ks2 = 0; ks2 < 4; ks2++) {
                    // B fragments: 4 x LDG.128 straight from L2-resident g_Wvh
                    const uint4* q = (const uint4*)(Bg + (ks2 >> 1) * 4096 + (ks2 & 1) * 2048);
                    const uint4 b0 = q[0], b1 = q[1], b2 = q[2], b3 = q[3];

                    const int kk = ks2 * 16 + 2 * tg;
                    uint32_t a[2][4];
#pragma unroll
                    for (int mf = 0; mf < 2; mf++) {
                        if (mf < nmf) {
                            const float* ar = A + (mf * 16 + g) * AP + kk;
                            const float2 f0 = *(const float2*)(ar);
                            const float2 f1 = *(const float2*)(ar + 8 * AP);
                            const float2 f2 = *(const float2*)(ar + 8);
                            const float2 f3 = *(const float2*)(ar + 8 * AP + 8);
                            a[mf][0] = pack_h2(f0.x, f0.y);
                            a[mf][1] = pack_h2(f1.x, f1.y);
                            a[mf][2] = pack_h2(f2.x, f2.y);
                            a[mf][3] = pack_h2(f3.x, f3.y);
                        }
                    }
#pragma unroll
                    for (int mf = 0; mf < 2; mf++) {
                        if (mf < nmf) {
                            mma16(acc[mf][0], a[mf], b0.x, b0.y);
                            mma16(acc[mf][1], a[mf], b0.z, b0.w);
                            mma16(acc[mf][2], a[mf], b1.x, b1.y);
                            mma16(acc[mf][3], a[mf], b1.z, b1.w);
                            mma16(acc[mf][4], a[mf], b2.x, b2.y);
                            mma16(acc[mf][5], a[mf], b2.z, b2.w);
                            mma16(acc[mf][6], a[mf], b3.x, b3.y);
                            mma16(acc[mf][7], a[mf], b3.z, b3.w);
                        }
                    }
                }
            }
        }

        // ---- score epilogue: relu(c+hp)*wa, reduce over 256 cols -> scS ----
        {
            float pA[2] = {0.0f, 0.0f}, pB[2] = {0.0f, 0.0f};
#pragma unroll
            for (int nf = 0; nf < 8; nf++) {
                const int col = warp_n * 64 + nf * 8 + 2 * tg;
                const float hp0 = hpS[col], hp1 = hpS[col + 1];
                const float wa0 = waS[col], wa1 = waS[col + 1];
#pragma unroll
                for (int mf = 0; mf < 2; mf++) {
                    if (mf < nmf) {
                        pA[mf] += fmaxf(acc[mf][nf][0] + hp0, 0.0f) * wa0
                                + fmaxf(acc[mf][nf][1] + hp1, 0.0f) * wa1;
                        pB[mf] += fmaxf(acc[mf][nf][2] + hp0, 0.0f) * wa0
                                + fmaxf(acc[mf][nf][3] + hp1, 0.0f) * wa1;
                        acc[mf][nf][0] = acc[mf][nf][1] = 0.0f;
                        acc[mf][nf][2] = acc[mf][nf][3] = 0.0f;
                    }
                }
            }
#pragma unroll
            for (int mf = 0; mf < 2; mf++) {
                if (mf < nmf) {
                    pA[mf] += __shfl_xor_sync(0xffffffffu, pA[mf], 1);
                    pA[mf] += __shfl_xor_sync(0xffffffffu, pA[mf], 2);
                    pB[mf] += __shfl_xor_sync(0xffffffffu, pB[mf], 1);
                    pB[mf] += __shfl_xor_sync(0xffffffffu, pB[mf], 2);
                    if (tg == 0) {
                        const int r0 = mc * MT + warp_m * 32 + mf * 16 + g;
                        atomicAdd(&scS[r0],     pA[mf]);
                        atomicAdd(&scS[r0 + 8], pB[mf]);
                    }
                }
            }
        }
        __syncthreads();

        // ---- online softmax state update (warp 0) ----
        if (wid == 0) {
            const int r0 = mc * MT;
            float s0 = (r0 + lane      < NR) ? scS[r0 + lane]      : -3.0e38f;
            float s1 = (r0 + 32 + lane < NR) ? scS[r0 + 32 + lane] : -3.0e38f;
            float mx = fmaxf(s0, s1);
#pragma unroll
            for (int off = 16; off; off >>= 1)
                mx = fmaxf(mx, __shfl_xor_sync(0xffffffffu, mx, off));
            const float Mold = misc[0];
            const float Mnew = fmaxf(Mold, mx);
            const float scl  = __expf(Mold - Mnew);
            const float e0 = __expf(s0 - Mnew);
            const float e1 = __expf(s1 - Mnew);
            esS[lane]      = e0;
            esS[32 + lane] = e1;
            float se = e0 + e1;
#pragma unroll
            for (int off = 16; off; off >>= 1)
                se += __shfl_xor_sync(0xffffffffu, se, off);
            if (lane == 0) {
                misc[1] = misc[1] * scl + se;
                misc[0] = Mnew;
                misc[2] = scl;
            }
        }
        __syncthreads();

        // ---- numerator accumulation from L2-hot rows of this chunk ----
        {
            const float scl = misc[2];
            const int nrr = (mc < 3) ? MT : (NR - 3 * MT);   // 64 or 4
            float4 s = make_float4(0.f, 0.f, 0.f, 0.f);
            for (int rr = 0; rr < nrr; rr++) {
                const float e = esS[rr];
                const float4 x = vb4[(size_t)(mc * MT + rr) * (DV / 4) + t];
                s.x = fmaf(e, x.x, s.x);
                s.y = fmaf(e, x.y, s.y);
                s.z = fmaf(e, x.z, s.z);
                s.w = fmaf(e, x.w, s.w);
            }
            num.x = fmaf(num.x, scl, s.x);
            num.y = fmaf(num.y, scl, s.y);
            num.z = fmaf(num.z, scl, s.z);
            num.w = fmaf(num.w, scl, s.w);
        }
        __syncthreads();
    }

    const float inv = 1.0f / misc[1];
    num.x *= inv; num.y *= inv; num.z *= inv; num.w *= inv;
    ((float4*)out)[(size_t)b * (DV / 4) + t] = num;
}

extern "C" void kernel_launch(void* const* d_in, const int* in_sizes, int n_in,
                              void* d_out, int out_size) {
    const float* visual = (const float*)d_in[0];
    const float* hidden = (const float*)d_in[1];
    const float* Wv     = (const float*)d_in[2];
    const float* bv     = (const float*)d_in[3];
    const float* Wh     = (const float*)d_in[4];
    const float* bh     = (const float*)d_in[5];
    const float* Wa     = (const float*)d_in[6];
    // d_in[7] = ba: additive constant over regions -> softmax-invariant, intentionally unused
    float* out = (float*)d_out;
    (void)in_sizes; (void)n_in; (void)out_size;

    cudaFuncSetAttribute(fused_kernel, cudaFuncAttributeMaxDynamicSharedMemorySize, SMEM_BYTES);

    setup_kernel<<<1024, DA>>>(Wv, hidden, Wh, bh);
    fused_kernel<<<NB, TPB, SMEM_BYTES>>>(visual, bv, Wa, out);
}

// round 14
// speedup vs baseline: 1.7109x; 1.7109x over previous
#include <cuda_runtime.h>
#include <cuda_fp16.h>
#include <cstdint>

#define NB 512
#define NR 196
#define DV 1024
#define DH 512
#define DA 256
#define KC 64
#define TPB 256
#define MT 64
#define APB 144                 // A smem row pitch BYTES (72 halves): STS/LDSM conflict-free
#define A_BYTES (MT * APB)      // 9216
#define B_BYTES 32768           // two 16KB fp16 frag-major kc-slices
#define STG_BYTES (A_BYTES + B_BYTES)
#define NCH 64                  // 4 M-chunks x 16 K-chunks
#define MISC_BYTES (DA * 4 * 3 + 64 * 4 + 32)
#define SMEM_BYTES (2 * STG_BYTES + MISC_BYTES)

__device__ uint32_t g_Wvh[DV * DA / 2];   // fp16 Wv frag-major [kc32][ks2][wn][nf][lane][b0,b1]
__device__ float g_hproj[NB * DA];

// ---------------- helpers ----------------
static __device__ __forceinline__ uint32_t smem_u32(const void* p) {
    uint32_t a;
    asm("{ .reg .u64 t; cvta.to.shared.u64 t, %1; cvt.u32.u64 %0, t; }" : "=r"(a) : "l"(p));
    return a;
}
static __device__ __forceinline__ void cpa16(uint32_t dst, const void* src) {
    asm volatile("cp.async.cg.shared.global [%0], [%1], 16;" :: "r"(dst), "l"(src));
}
static __device__ __forceinline__ void cpa_commit() {
    asm volatile("cp.async.commit_group;" ::: "memory");
}
template <int N> static __device__ __forceinline__ void cpa_wait() {
    asm volatile("cp.async.wait_group %0;" :: "n"(N) : "memory");
}
static __device__ __forceinline__ uint32_t pack_h2(float lo, float hi) {
    __half2 h = __floats2half2_rn(lo, hi);
    return *(uint32_t*)&h;
}
static __device__ __forceinline__ void ldsm4(uint32_t* a, uint32_t addr) {
    asm volatile("ldmatrix.sync.aligned.m8n8.x4.shared.b16 {%0,%1,%2,%3}, [%4];"
                 : "=r"(a[0]), "=r"(a[1]), "=r"(a[2]), "=r"(a[3]) : "r"(addr));
}
static __device__ __forceinline__ void sts128(uint32_t dst, uint32_t x, uint32_t y,
                                              uint32_t z, uint32_t w) {
    asm volatile("st.shared.v4.b32 [%0], {%1,%2,%3,%4};"
                 :: "r"(dst), "r"(x), "r"(y), "r"(z), "r"(w) : "memory");
}
static __device__ __forceinline__ void mma16(float* c, const uint32_t* a, uint32_t b0, uint32_t b1) {
    asm volatile(
        "mma.sync.aligned.m16n8k16.row.col.f32.f16.f16.f32 "
        "{%0,%1,%2,%3}, {%4,%5,%6,%7}, {%8,%9}, {%0,%1,%2,%3};"
        : "+f"(c[0]), "+f"(c[1]), "+f"(c[2]), "+f"(c[3])
        : "r"(a[0]), "r"(a[1]), "r"(a[2]), "r"(a[3]), "r"(b0), "r"(b1));
}

// ---------------- setup: Wv->fp16 frag-major (proven R11 layout) + hproj ----------------
// u32 entry r = kc32*4096 + ks2*2048 + wn*512 + nf*64 + lane*2 + breg
__global__ __launch_bounds__(DA) void setup_kernel(
    const float* __restrict__ Wv,
    const float* __restrict__ hidden, const float* __restrict__ Wh,
    const float* __restrict__ bh)
{
    if (blockIdx.x < 512) {
        const int r = blockIdx.x * DA + threadIdx.x;
        const int breg = r & 1;
        const int lane = (r >> 1) & 31;
        const int nf   = (r >> 6) & 7;
        const int wn   = (r >> 9) & 3;
        const int ks2  = (r >> 11) & 1;
        const int kc   = r >> 12;
        const int col = wn * 64 + nf * 8 + (lane >> 2);
        const int k0  = kc * 32 + ks2 * 16 + 2 * (lane & 3) + breg * 8;
        g_Wvh[r] = pack_h2(Wv[k0 * DA + col], Wv[(k0 + 1) * DA + col]);
    } else {
        const int b = blockIdx.x - 512, a = threadIdx.x;
        const float* h = hidden + b * DH;
        const float* w = Wh + a;
        float acc = bh[a];
#pragma unroll 8
        for (int k = 0; k < DH; k++) acc = fmaf(h[k], w[k * DA], acc);
        g_hproj[b * DA + a] = acc;
    }
}

// ---------------- A prefetch (GMEM->regs), convert+store (regs->fp16 smem) ----------------
static __device__ __forceinline__ void ldgA(int idx, float4* pf,
                                            const float* __restrict__ vb, int t) {
    const int mc = idx >> 4, kc = idx & 15;
    const int row = t >> 2, kseg = t & 3;
    const int gr = mc * MT + row;
    if (gr < NR) {
        const float4* s = (const float4*)(vb + (size_t)gr * DV + kc * KC + kseg * 16);
        pf[0] = s[0]; pf[1] = s[1]; pf[2] = s[2]; pf[3] = s[3];
    } else {
        pf[0] = pf[1] = pf[2] = pf[3] = make_float4(0.f, 0.f, 0.f, 0.f);
    }
}
static __device__ __forceinline__ void stsA(int idx, const float4* pf, uint32_t sS, int t) {
    const int buf = idx & 1;
    const int row = t >> 2, kseg = t & 3;
    const uint32_t dst = sS + (uint32_t)buf * STG_BYTES + row * APB + kseg * 32;
    sts128(dst,      pack_h2(pf[0].x, pf[0].y), pack_h2(pf[0].z, pf[0].w),
                     pack_h2(pf[1].x, pf[1].y), pack_h2(pf[1].z, pf[1].w));
    sts128(dst + 16, pack_h2(pf[2].x, pf[2].y), pack_h2(pf[2].z, pf[2].w),
                     pack_h2(pf[3].x, pf[3].y), pack_h2(pf[3].z, pf[3].w));
}
static __device__ __forceinline__ void stageB(int idx, uint32_t sS, int t) {
    const int kc = idx & 15, buf = idx & 1;
    const uint32_t* bsrc = g_Wvh + (size_t)(2 * kc) * 4096;
    const uint32_t bB = sS + (uint32_t)buf * STG_BYTES + A_BYTES;
#pragma unroll
    for (int i = 0; i < 8; i++) {
        int s = t + i * TPB;
        cpa16(bB + s * 16, bsrc + s * 4);
    }
}

// ---------------- fused: 1 CTA/batch, 2 CTAs/SM, fp16-A LDSM, 1 barrier/chunk ----------------
__global__ __launch_bounds__(TPB, 2) void fused_kernel(
    const float* __restrict__ visual,
    const float* __restrict__ bv,
    const float* __restrict__ Wa,
    float* __restrict__ out)
{
    extern __shared__ char smem[];
    float* hpS  = (float*)(smem + 2 * STG_BYTES);
    float* waS  = hpS + DA;
    float* scS  = waS + DA;
    float* esS  = scS + DA;                      // 64 exp weights of current chunk
    float* misc = esS + 64;                      // [0]=max,[1]=den,[2]=scale

    const int b = blockIdx.x, t = threadIdx.x;
    const int wid = t >> 5, lane = t & 31, g = lane >> 2, tg = lane & 3;
    const int warp_m = wid >> 2, warp_n = wid & 3;    // 2x4 warps: 64 rows x 256 cols
    const float* vb = visual + (size_t)b * NR * DV;
    const float4* vb4 = (const float4*)vb;

    hpS[t] = g_hproj[b * DA + t] + bv[t];
    waS[t] = Wa[t];
    scS[t] = 0.0f;
    if (t == 0) { misc[0] = -3.0e38f; misc[1] = 0.0f; misc[2] = 0.0f; }

    const uint32_t sS = smem_u32(smem);
    // ldmatrix lane source: row (lane&15), k-halfbyte (lane>>4)*16
    const uint32_t lmLane = (uint32_t)((lane & 15) * APB + (lane >> 4) * 16);

    float4 pf[4];
    ldgA(0, pf, vb, t);
    stageB(0, sS, t); cpa_commit();
    stsA(0, pf, sS, t);
    cpa_wait<0>();
    __syncthreads();

    float acc[2][8][4];
#pragma unroll
    for (int mf = 0; mf < 2; mf++)
#pragma unroll
        for (int nf = 0; nf < 8; nf++)
#pragma unroll
            for (int i = 0; i < 4; i++) acc[mf][nf][i] = 0.0f;

    float4 num = make_float4(0.f, 0.f, 0.f, 0.f);

#pragma unroll 1
    for (int mc = 0; mc < 4; mc++) {
        const int nmf = (mc == 3) ? ((warp_m == 0) ? 1 : 0) : 2;

        for (int kc = 0; kc < 16; kc++) {
            const int idx = mc * 16 + kc;
            const bool more = (idx + 1 < NCH);
            if (more) {
                ldgA(idx + 1, pf, vb, t);            // prefetch A(i+1) to regs
                stageB(idx + 1, sS, t);              // cp.async B(i+1) into buf^1
                cpa_commit();
            }

            if (nmf > 0) {
                const int buf = idx & 1;
                const uint32_t aW = sS + (uint32_t)buf * STG_BYTES
                                  + (uint32_t)(warp_m * 32) * APB + lmLane;
                const uint2* Bw = (const uint2*)(smem + buf * STG_BYTES + A_BYTES)
                                  + (warp_n * 8) * 32 + lane;
#pragma unroll
                for (int ks2 = 0; ks2 < 4; ks2++) {
                    uint32_t a[2][4];
#pragma unroll
                    for (int mf = 0; mf < 2; mf++)
                        if (mf < nmf) ldsm4(a[mf], aW + mf * (16 * APB) + ks2 * 32);
                    const uint2* Bk = Bw + ks2 * 1024;
#pragma unroll
                    for (int nf = 0; nf < 8; nf++) {
                        const uint2 bb = Bk[nf * 32];
#pragma unroll
                        for (int mf = 0; mf < 2; mf++)
                            if (mf < nmf) mma16(acc[mf][nf], a[mf], bb.x, bb.y);
                    }
                }
            }

            if (more) {
                stsA(idx + 1, pf, sS, t);            // publish A(i+1) to buf^1
                cpa_wait<0>();                       // B(i+1) landed
            }
            __syncthreads();                         // single barrier: publish i+1, drain i-1
        }

        // ---- score epilogue: relu(c+hp)*wa, reduce over 256 cols -> scS ----
        {
            float pA[2] = {0.0f, 0.0f}, pB[2] = {0.0f, 0.0f};
#pragma unroll
            for (int nf = 0; nf < 8; nf++) {
                const int col = warp_n * 64 + nf * 8 + 2 * tg;
                const float hp0 = hpS[col], hp1 = hpS[col + 1];
                const float wa0 = waS[col], wa1 = waS[col + 1];
#pragma unroll
                for (int mf = 0; mf < 2; mf++) {
                    if (mf < nmf) {
                        pA[mf] += fmaxf(acc[mf][nf][0] + hp0, 0.0f) * wa0
                                + fmaxf(acc[mf][nf][1] + hp1, 0.0f) * wa1;
                        pB[mf] += fmaxf(acc[mf][nf][2] + hp0, 0.0f) * wa0
                                + fmaxf(acc[mf][nf][3] + hp1, 0.0f) * wa1;
                        acc[mf][nf][0] = acc[mf][nf][1] = 0.0f;
                        acc[mf][nf][2] = acc[mf][nf][3] = 0.0f;
                    }
                }
            }
#pragma unroll
            for (int mf = 0; mf < 2; mf++) {
                if (mf < nmf) {
                    pA[mf] += __shfl_xor_sync(0xffffffffu, pA[mf], 1);
                    pA[mf] += __shfl_xor_sync(0xffffffffu, pA[mf], 2);
                    pB[mf] += __shfl_xor_sync(0xffffffffu, pB[mf], 1);
                    pB[mf] += __shfl_xor_sync(0xffffffffu, pB[mf], 2);
                    if (tg == 0) {
                        const int r0 = mc * MT + warp_m * 32 + mf * 16 + g;
                        atomicAdd(&scS[r0],     pA[mf]);
                        atomicAdd(&scS[r0 + 8], pB[mf]);
                    }
                }
            }
        }
        __syncthreads();       // scores of this chunk final

        // ---- online softmax state update (warp 0) ----
        if (wid == 0) {
            const int r0 = mc * MT;
            float s0 = (r0 + lane      < NR) ? scS[r0 + lane]      : -3.0e38f;
            float s1 = (r0 + 32 + lane < NR) ? scS[r0 + 32 + lane] : -3.0e38f;
            float mx = fmaxf(s0, s1);
#pragma unroll
            for (int off = 16; off; off >>= 1)
                mx = fmaxf(mx, __shfl_xor_sync(0xffffffffu, mx, off));
            const float Mold = misc[0];
            const float Mnew = fmaxf(Mold, mx);
            const float scl  = __expf(Mold - Mnew);
            const float e0 = __expf(s0 - Mnew);
            const float e1 = __expf(s1 - Mnew);
            esS[lane]      = e0;
            esS[32 + lane] = e1;
            float se = e0 + e1;
#pragma unroll
            for (int off = 16; off; off >>= 1)
                se += __shfl_xor_sync(0xffffffffu, se, off);
            if (lane == 0) {
                misc[1] = misc[1] * scl + se;
                misc[0] = Mnew;
                misc[2] = scl;
            }
        }
        __syncthreads();

        // ---- numerator accumulation from L2-hot rows of this chunk ----
        {
            const float scl = misc[2];
            const int nrr = (mc < 3) ? MT : (NR - 3 * MT);   // 64 or 4
            float4 s = make_float4(0.f, 0.f, 0.f, 0.f);
            for (int rr = 0; rr < nrr; rr++) {
                const float e = esS[rr];
                const float4 x = vb4[(size_t)(mc * MT + rr) * (DV / 4) + t];
                s.x = fmaf(e, x.x, s.x);
                s.y = fmaf(e, x.y, s.y);
                s.z = fmaf(e, x.z, s.z);
                s.w = fmaf(e, x.w, s.w);
            }
            num.x = fmaf(num.x, scl, s.x);
            num.y = fmaf(num.y, scl, s.y);
            num.z = fmaf(num.z, scl, s.z);
            num.w = fmaf(num.w, scl, s.w);
        }
        __syncthreads();       // esS/misc stable before next chunk's epilogue
    }

    const float inv = 1.0f / misc[1];
    num.x *= inv; num.y *= inv; num.z *= inv; num.w *= inv;
    ((float4*)out)[(size_t)b * (DV / 4) + t] = num;
}

extern "C" void kernel_launch(void* const* d_in, const int* in_sizes, int n_in,
                              void* d_out, int out_size) {
    const float* visual = (const float*)d_in[0];
    const float* hidden = (const float*)d_in[1];
    const float* Wv     = (const float*)d_in[2];
    const float* bv     = (const float*)d_in[3];
    const float* Wh     = (const float*)d_in[4];
    const float* bh     = (const float*)d_in[5];
    const float* Wa     = (const float*)d_in[6];
    // d_in[7] = ba: additive constant over regions -> softmax-invariant, intentionally unused
    float* out = (float*)d_out;
    (void)in_sizes; (void)n_in; (void)out_size;

    cudaFuncSetAttribute(fused_kernel, cudaFuncAttributeMaxDynamicSharedMemorySize, SMEM_BYTES);

    setup_kernel<<<1024, DA>>>(Wv, hidden, Wh, bh);
    fused_kernel<<<NB, TPB, SMEM_BYTES>>>(visual, bv, Wa, out);
}

// round 15
// speedup vs baseline: 1.8034x; 1.0540x over previous
#include <cuda_runtime.h>
#include <cuda_fp16.h>
#include <cstdint>

#define NB 512
#define NR 196
#define DV 1024
#define DH 512
#define DA 256
#define KC 64
#define TPB 256
#define MT 64
#define APB 144                 // A smem row pitch BYTES
#define A_BYTES (MT * APB)      // 9216
#define B_BYTES 32768
#define STG_BYTES (A_BYTES + B_BYTES)
#define NCH 64                  // 4 M-chunks x 16 K-chunks
#define MISC_BYTES (DA * 4 * 3 + 128 * 4 + 32)
#define SMEM_BYTES (2 * STG_BYTES + MISC_BYTES)

__device__ uint32_t g_Wvh[DV * DA / 2];   // fp16 Wv frag-major [kc32][ks2][wn][nfpair][lane][4]
__device__ float g_hproj[NB * DA];

// ---------------- helpers ----------------
static __device__ __forceinline__ uint32_t smem_u32(const void* p) {
    uint32_t a;
    asm("{ .reg .u64 t; cvta.to.shared.u64 t, %1; cvt.u32.u64 %0, t; }" : "=r"(a) : "l"(p));
    return a;
}
static __device__ __forceinline__ void cpa16(uint32_t dst, const void* src) {
    asm volatile("cp.async.cg.shared.global [%0], [%1], 16;" :: "r"(dst), "l"(src));
}
static __device__ __forceinline__ void cpa_commit() {
    asm volatile("cp.async.commit_group;" ::: "memory");
}
template <int N> static __device__ __forceinline__ void cpa_wait() {
    asm volatile("cp.async.wait_group %0;" :: "n"(N) : "memory");
}
static __device__ __forceinline__ uint32_t pack_h2(float lo, float hi) {
    __half2 h = __floats2half2_rn(lo, hi);
    return *(uint32_t*)&h;
}
static __device__ __forceinline__ void ldsm4(uint32_t* a, uint32_t addr) {
    asm volatile("ldmatrix.sync.aligned.m8n8.x4.shared.b16 {%0,%1,%2,%3}, [%4];"
                 : "=r"(a[0]), "=r"(a[1]), "=r"(a[2]), "=r"(a[3]) : "r"(addr));
}
static __device__ __forceinline__ void sts128(uint32_t dst, uint32_t x, uint32_t y,
                                              uint32_t z, uint32_t w) {
    asm volatile("st.shared.v4.b32 [%0], {%1,%2,%3,%4};"
                 :: "r"(dst), "r"(x), "r"(y), "r"(z), "r"(w) : "memory");
}
static __device__ __forceinline__ void mma16(float* c, const uint32_t* a, uint32_t b0, uint32_t b1) {
    asm volatile(
        "mma.sync.aligned.m16n8k16.row.col.f32.f16.f16.f32 "
        "{%0,%1,%2,%3}, {%4,%5,%6,%7}, {%8,%9}, {%0,%1,%2,%3};"
        : "+f"(c[0]), "+f"(c[1]), "+f"(c[2]), "+f"(c[3])
        : "r"(a[0]), "r"(a[1]), "r"(a[2]), "r"(a[3]), "r"(b0), "r"(b1));
}

// ---------------- setup: Wv->fp16 paired-nf frag-major + hproj ----------------
// u32 entry r = kc32*4096 + ks2*2048 + wn*512 + p*128 + lane*4 + q
// nf = 2p + (q>>1), breg = q&1
// col = wn*64+nf*8+(lane>>2);  k0 = kc*32+ks2*16+2*(lane&3)+breg*8
__global__ __launch_bounds__(DA) void setup_kernel(
    const float* __restrict__ Wv,
    const float* __restrict__ hidden, const float* __restrict__ Wh,
    const float* __restrict__ bh)
{
    if (blockIdx.x < 512) {
        const int r = blockIdx.x * DA + threadIdx.x;
        const int q    = r & 3;
        const int lane = (r >> 2) & 31;
        const int p    = (r >> 7) & 3;
        const int wn   = (r >> 9) & 3;
        const int ks2  = (r >> 11) & 1;
        const int kc   = r >> 12;
        const int nf   = 2 * p + (q >> 1);
        const int breg = q & 1;
        const int col = wn * 64 + nf * 8 + (lane >> 2);
        const int k0  = kc * 32 + ks2 * 16 + 2 * (lane & 3) + breg * 8;
        g_Wvh[r] = pack_h2(Wv[k0 * DA + col], Wv[(k0 + 1) * DA + col]);
    } else {
        const int b = blockIdx.x - 512, a = threadIdx.x;
        const float* h = hidden + b * DH;
        const float* w = Wh + a;
        float acc = bh[a];
#pragma unroll 8
        for (int k = 0; k < DH; k++) acc = fmaf(h[k], w[k * DA], acc);
        g_hproj[b * DA + a] = acc;
    }
}

// ---------------- A prefetch / fp16 convert+store / B stage ----------------
static __device__ __forceinline__ void ldgA(int idx, float4* pf,
                                            const float* __restrict__ vb, int t) {
    const int mc = idx >> 4, kc = idx & 15;
    const int row = t >> 2, kseg = t & 3;
    const int gr = mc * MT + row;
    if (gr < NR) {
        const float4* s = (const float4*)(vb + (size_t)gr * DV + kc * KC + kseg * 16);
        pf[0] = s[0]; pf[1] = s[1]; pf[2] = s[2]; pf[3] = s[3];
    } else {
        pf[0] = pf[1] = pf[2] = pf[3] = make_float4(0.f, 0.f, 0.f, 0.f);
    }
}
static __device__ __forceinline__ void stsA(int idx, const float4* pf, uint32_t sS, int t) {
    const int buf = idx & 1;
    const int row = t >> 2, kseg = t & 3;
    const uint32_t dst = sS + (uint32_t)buf * STG_BYTES + row * APB + kseg * 32;
    sts128(dst,      pack_h2(pf[0].x, pf[0].y), pack_h2(pf[0].z, pf[0].w),
                     pack_h2(pf[1].x, pf[1].y), pack_h2(pf[1].z, pf[1].w));
    sts128(dst + 16, pack_h2(pf[2].x, pf[2].y), pack_h2(pf[2].z, pf[2].w),
                     pack_h2(pf[3].x, pf[3].y), pack_h2(pf[3].z, pf[3].w));
}
static __device__ __forceinline__ void stageB(int idx, uint32_t sS, int t) {
    const int kc = idx & 15, buf = idx & 1;
    const uint32_t* bsrc = g_Wvh + (size_t)(2 * kc) * 4096;
    const uint32_t bB = sS + (uint32_t)buf * STG_BYTES + A_BYTES;
#pragma unroll
    for (int i = 0; i < 8; i++) {
        int s = t + i * TPB;
        cpa16(bB + s * 16, bsrc + s * 4);
    }
}

// ---------------- fused: interleaved numerator, paired-nf B, 1 barrier/chunk ----------------
__global__ __launch_bounds__(TPB, 2) void fused_kernel(
    const float* __restrict__ visual,
    const float* __restrict__ bv,
    const float* __restrict__ Wa,
    float* __restrict__ out)
{
    extern __shared__ char smem[];
    float* hpS  = (float*)(smem + 2 * STG_BYTES);
    float* waS  = hpS + DA;
    float* scS  = waS + DA;
    float* esS  = scS + DA;                      // 2 x 64 exp weights (double-buffered by mc&1)
    float* misc = esS + 128;                     // [0]=max,[1]=den,[2]=scale

    const int b = blockIdx.x, t = threadIdx.x;
    const int wid = t >> 5, lane = t & 31, g = lane >> 2, tg = lane & 3;
    const int warp_m = wid >> 2, warp_n = wid & 3;    // 2x4 warps: 64 rows x 256 cols
    const float* vb = visual + (size_t)b * NR * DV;
    const float4* vb4 = (const float4*)vb;

    hpS[t] = g_hproj[b * DA + t] + bv[t];
    waS[t] = Wa[t];
    scS[t] = 0.0f;
    if (t == 0) { misc[0] = -3.0e38f; misc[1] = 0.0f; misc[2] = 0.0f; }

    const uint32_t sS = smem_u32(smem);
    const uint32_t lmLane = (uint32_t)((lane & 15) * APB + (lane >> 4) * 16);

    float4 pf[4];
    ldgA(0, pf, vb, t);
    stageB(0, sS, t); cpa_commit();
    stsA(0, pf, sS, t);
    cpa_wait<0>();
    __syncthreads();

    float acc[2][8][4];
#pragma unroll
    for (int mf = 0; mf < 2; mf++)
#pragma unroll
        for (int nf = 0; nf < 8; nf++)
#pragma unroll
            for (int i = 0; i < 4; i++) acc[mf][nf][i] = 0.0f;

    float4 num = make_float4(0.f, 0.f, 0.f, 0.f);

#pragma unroll 1
    for (int mc = 0; mc < 4; mc++) {
        const int nmf = (mc == 3) ? ((warp_m == 0) ? 1 : 0) : 2;
        const float* esP = esS + ((mc - 1) & 1) * 64;    // prev chunk's exp weights

        for (int kc = 0; kc < 16; kc++) {
            const int idx = mc * 16 + kc;
            const bool more = (idx + 1 < NCH);
            if (more) {
                ldgA(idx + 1, pf, vb, t);            // prefetch A(i+1) to regs
                stageB(idx + 1, sS, t);              // cp.async B(i+1) into buf^1
                cpa_commit();
            }

            // ---- interleaved numerator of previous mc (4 rows per kc iter) ----
            if (mc > 0) {
                const int rbase = (mc - 1) * MT + kc * 4;
#pragma unroll
                for (int rr = 0; rr < 4; rr++) {
                    const float e = esP[kc * 4 + rr];
                    const float4 x = vb4[(size_t)(rbase + rr) * (DV / 4) + t];
                    num.x = fmaf(e, x.x, num.x);
                    num.y = fmaf(e, x.y, num.y);
                    num.z = fmaf(e, x.z, num.z);
                    num.w = fmaf(e, x.w, num.w);
                }
            }

            if (nmf > 0) {
                const int buf = idx & 1;
                const uint32_t aW = sS + (uint32_t)buf * STG_BYTES
                                  + (uint32_t)(warp_m * 32) * APB + lmLane;
                const uint4* Bw = (const uint4*)(smem + buf * STG_BYTES + A_BYTES)
                                  + warp_n * 128 + lane;    // [wn][p][lane] in uint4
#pragma unroll
                for (int ks2 = 0; ks2 < 4; ks2++) {
                    uint32_t a[2][4];
#pragma unroll
                    for (int mf = 0; mf < 2; mf++)
                        if (mf < nmf) ldsm4(a[mf], aW + mf * (16 * APB) + ks2 * 32);
                    const uint4* Bk = Bw + ks2 * 512;
#pragma unroll
                    for (int p = 0; p < 4; p++) {
                        const uint4 bb = Bk[p * 32];
#pragma unroll
                        for (int mf = 0; mf < 2; mf++) {
                            if (mf < nmf) {
                                mma16(acc[mf][2 * p],     a[mf], bb.x, bb.y);
                                mma16(acc[mf][2 * p + 1], a[mf], bb.z, bb.w);
                            }
                        }
                    }
                }
            }

            if (more) {
                stsA(idx + 1, pf, sS, t);            // publish A(i+1) to buf^1
                cpa_wait<0>();                       // B(i+1) landed
            }
            __syncthreads();                         // single barrier per chunk
        }

        // ---- score epilogue: relu(c+hp)*wa, reduce over 256 cols -> scS ----
        {
            float pA[2] = {0.0f, 0.0f}, pB[2] = {0.0f, 0.0f};
#pragma unroll
            for (int nf = 0; nf < 8; nf++) {
                const int col = warp_n * 64 + nf * 8 + 2 * tg;
                const float hp0 = hpS[col], hp1 = hpS[col + 1];
                const float wa0 = waS[col], wa1 = waS[col + 1];
#pragma unroll
                for (int mf = 0; mf < 2; mf++) {
                    if (mf < nmf) {
                        pA[mf] += fmaxf(acc[mf][nf][0] + hp0, 0.0f) * wa0
                                + fmaxf(acc[mf][nf][1] + hp1, 0.0f) * wa1;
                        pB[mf] += fmaxf(acc[mf][nf][2] + hp0, 0.0f) * wa0
                                + fmaxf(acc[mf][nf][3] + hp1, 0.0f) * wa1;
                        acc[mf][nf][0] = acc[mf][nf][1] = 0.0f;
                        acc[mf][nf][2] = acc[mf][nf][3] = 0.0f;
                    }
                }
            }
#pragma unroll
            for (int mf = 0; mf < 2; mf++) {
                if (mf < nmf) {
                    pA[mf] += __shfl_xor_sync(0xffffffffu, pA[mf], 1);
                    pA[mf] += __shfl_xor_sync(0xffffffffu, pA[mf], 2);
                    pB[mf] += __shfl_xor_sync(0xffffffffu, pB[mf], 1);
                    pB[mf] += __shfl_xor_sync(0xffffffffu, pB[mf], 2);
                    if (tg == 0) {
                        const int r0 = mc * MT + warp_m * 32 + mf * 16 + g;
                        atomicAdd(&scS[r0],     pA[mf]);
                        atomicAdd(&scS[r0 + 8], pB[mf]);
                    }
                }
            }
        }
        __syncthreads();       // scores of this chunk final

        // ---- online softmax state update (warp 0), es -> buffer mc&1 ----
        if (wid == 0) {
            float* esH = esS + (mc & 1) * 64;
            const int r0 = mc * MT;
            float s0 = (r0 + lane      < NR) ? scS[r0 + lane]      : -3.0e38f;
            float s1 = (r0 + 32 + lane < NR) ? scS[r0 + 32 + lane] : -3.0e38f;
            float mx = fmaxf(s0, s1);
#pragma unroll
            for (int off = 16; off; off >>= 1)
                mx = fmaxf(mx, __shfl_xor_sync(0xffffffffu, mx, off));
            const float Mold = misc[0];
            const float Mnew = fmaxf(Mold, mx);
            const float scl  = __expf(Mold - Mnew);
            const float e0 = __expf(s0 - Mnew);
            const float e1 = __expf(s1 - Mnew);
            esH[lane]      = e0;
            esH[32 + lane] = e1;
            float se = e0 + e1;
#pragma unroll
            for (int off = 16; off; off >>= 1)
                se += __shfl_xor_sync(0xffffffffu, se, off);
            if (lane == 0) {
                misc[1] = misc[1] * scl + se;
                misc[0] = Mnew;
                misc[2] = scl;
            }
        }
        __syncthreads();

        // ---- rescale running numerator by this chunk's scale factor ----
        {
            const float scl = misc[2];
            num.x *= scl; num.y *= scl; num.z *= scl; num.w *= scl;
        }
        // (no extra barrier: next misc write is fenced by mc+1's epilogue barriers)
    }

    // ---- drain numerator of last chunk (rows 192..195) ----
    {
        const float* esP = esS + (3 & 1) * 64;
#pragma unroll
        for (int rr = 0; rr < NR - 3 * MT; rr++) {
            const float e = esP[rr];
            const float4 x = vb4[(size_t)(3 * MT + rr) * (DV / 4) + t];
            num.x = fmaf(e, x.x, num.x);
            num.y = fmaf(e, x.y, num.y);
            num.z = fmaf(e, x.z, num.z);
            num.w = fmaf(e, x.w, num.w);
        }
    }

    const float inv = 1.0f / misc[1];
    num.x *= inv; num.y *= inv; num.z *= inv; num.w *= inv;
    ((float4*)out)[(size_t)b * (DV / 4) + t] = num;
}

extern "C" void kernel_launch(void* const* d_in, const int* in_sizes, int n_in,
                              void* d_out, int out_size) {
    const float* visual = (const float*)d_in[0];
    const float* hidden = (const float*)d_in[1];
    const float* Wv     = (const float*)d_in[2];
    const float* bv     = (const float*)d_in[3];
    const float* Wh     = (const float*)d_in[4];
    const float* bh     = (const float*)d_in[5];
    const float* Wa     = (const float*)d_in[6];
    // d_in[7] = ba: additive constant over regions -> softmax-invariant, intentionally unused
    float* out = (float*)d_out;
    (void)in_sizes; (void)n_in; (void)out_size;

    cudaFuncSetAttribute(fused_kernel, cudaFuncAttributeMaxDynamicSharedMemorySize, SMEM_BYTES);

    setup_kernel<<<1024, DA>>>(Wv, hidden, Wh, bh);
    fused_kernel<<<NB, TPB, SMEM_BYTES>>>(visual, bv, Wa, out);
}